// round 1
// baseline (speedup 1.0000x reference)
#include <cuda_runtime.h>
#include <cstddef>

#define BATCH 4
#define SEQ   4096
#define DIM   512

// ---------------- scratch (device globals: allocation-free) ----------------
__device__ float g_K [BATCH * SEQ * DIM];              // 32 MB
__device__ float g_Q [BATCH * SEQ * DIM];              // 32 MB
__device__ float g_V [BATCH * SEQ * DIM];              // 32 MB
__device__ float g_Vt[BATCH * DIM * SEQ];              // 32 MB (V transposed per batch)
__device__ float g_P [(size_t)BATCH * SEQ * SEQ];      // 268 MB (scores, then softmax in place)

// ---------------------------------------------------------------------------
// Generic tiled SGEMM computing C[m,n] = alpha * sum_k A[m,k] * B[n,k]
// A: M x K row-major (ld = K), B: N x K row-major (ld = K), C: M x N (ld = N).
// If SCORES: epilogue applies scatter mask on column n (mask[n]==0 -> -1e12).
// Dims are guaranteed multiples of the tile sizes here (no bounds checks).
// BM = BN = 128, BK = 8, 256 threads, 8x8 accumulators per thread.
// ---------------------------------------------------------------------------
template <bool SCORES>
__global__ __launch_bounds__(256, 2)
void gemm_abt_kernel(const float* __restrict__ A,
                     const float* __restrict__ B,
                     float* __restrict__ C,
                     int M, int N, int K,
                     float alpha,
                     const int* __restrict__ mask)
{
    __shared__ float As[8][128];
    __shared__ float Bs[8][128];

    const int bm  = blockIdx.y * 128;
    const int bn  = blockIdx.x * 128;
    const int tid = threadIdx.x;          // 0..255
    const int tx  = tid & 15;             // 0..15 -> 8 cols each
    const int ty  = tid >> 4;             // 0..15 -> 8 rows each

    // Global->shared load mapping: 128 rows x 8 k = 1024 floats = 256 x float4
    const int lrow = tid >> 1;            // 0..127
    const int lk4  = (tid & 1) * 4;       // 0 or 4

    const float* Aptr = A + (size_t)(bm + lrow) * K + lk4;
    const float* Bptr = B + (size_t)(bn + lrow) * K + lk4;

    float acc[8][8];
    #pragma unroll
    for (int i = 0; i < 8; i++)
        #pragma unroll
        for (int j = 0; j < 8; j++)
            acc[i][j] = 0.0f;

    for (int k0 = 0; k0 < K; k0 += 8) {
        const float4 av = *(const float4*)(Aptr + k0);
        const float4 bv = *(const float4*)(Bptr + k0);

        __syncthreads();   // previous tile's reads complete before overwrite
        As[lk4 + 0][lrow] = av.x;
        As[lk4 + 1][lrow] = av.y;
        As[lk4 + 2][lrow] = av.z;
        As[lk4 + 3][lrow] = av.w;
        Bs[lk4 + 0][lrow] = bv.x;
        Bs[lk4 + 1][lrow] = bv.y;
        Bs[lk4 + 2][lrow] = bv.z;
        Bs[lk4 + 3][lrow] = bv.w;
        __syncthreads();

        #pragma unroll
        for (int k = 0; k < 8; k++) {
            float a[8], b[8];
            *(float4*)(a)     = *(const float4*)&As[k][ty * 8];
            *(float4*)(a + 4) = *(const float4*)&As[k][ty * 8 + 4];
            *(float4*)(b)     = *(const float4*)&Bs[k][tx * 8];
            *(float4*)(b + 4) = *(const float4*)&Bs[k][tx * 8 + 4];
            #pragma unroll
            for (int i = 0; i < 8; i++)
                #pragma unroll
                for (int j = 0; j < 8; j++)
                    acc[i][j] += a[i] * b[j];
        }
    }

    // Epilogue
    #pragma unroll
    for (int i = 0; i < 8; i++) {
        const int m = bm + ty * 8 + i;
        float* crow = C + (size_t)m * N + bn + tx * 8;
        #pragma unroll
        for (int j = 0; j < 8; j++) {
            float v = acc[i][j] * alpha;
            if (SCORES) {
                const int n = bn + tx * 8 + j;
                if (mask[n] == 0) v = -1e12f;
            }
            crow[j] = v;
        }
    }
}

// ---------------------------------------------------------------------------
// Per-batch transpose: Vt[b][d][t] = V[b][t][d]
// grid: (DIM/32, SEQ/32, BATCH), block: (32, 8)
// ---------------------------------------------------------------------------
__global__ void transpose_v_kernel(const float* __restrict__ Vin,
                                   float* __restrict__ Vt)
{
    __shared__ float tile[32][33];
    const int b = blockIdx.z;
    const float* V = Vin + (size_t)b * SEQ * DIM;
    float*       O = Vt  + (size_t)b * DIM * SEQ;
    const int d0 = blockIdx.x * 32;
    const int t0 = blockIdx.y * 32;

    #pragma unroll
    for (int r = 0; r < 32; r += 8)
        tile[threadIdx.y + r][threadIdx.x] =
            V[(size_t)(t0 + threadIdx.y + r) * DIM + d0 + threadIdx.x];
    __syncthreads();
    #pragma unroll
    for (int r = 0; r < 32; r += 8)
        O[(size_t)(d0 + threadIdx.y + r) * SEQ + t0 + threadIdx.x] =
            tile[threadIdx.x][threadIdx.y + r];
}

// ---------------------------------------------------------------------------
// Row softmax over length-SEQ rows of g_P, in place. One 256-thread CTA/row,
// 16 elements per thread held in registers (one global read + one write).
// grid: BATCH*SEQ rows.
// ---------------------------------------------------------------------------
__global__ __launch_bounds__(256)
void softmax_rows_kernel(float* __restrict__ P)
{
    float* p = P + (size_t)blockIdx.x * SEQ;
    const int tid  = threadIdx.x;
    const int lane = tid & 31;
    const int warp = tid >> 5;
    __shared__ float sred[8];

    float v[16];
    float m = -3.402823466e+38f;
    #pragma unroll
    for (int i = 0; i < 16; i++) {
        v[i] = p[tid + i * 256];
        m = fmaxf(m, v[i]);
    }
    #pragma unroll
    for (int off = 16; off > 0; off >>= 1)
        m = fmaxf(m, __shfl_xor_sync(0xffffffffu, m, off));
    if (lane == 0) sred[warp] = m;
    __syncthreads();
    m = sred[0];
    #pragma unroll
    for (int w = 1; w < 8; w++) m = fmaxf(m, sred[w]);
    __syncthreads();

    float s = 0.0f;
    #pragma unroll
    for (int i = 0; i < 16; i++) {
        v[i] = __expf(v[i] - m);
        s += v[i];
    }
    #pragma unroll
    for (int off = 16; off > 0; off >>= 1)
        s += __shfl_xor_sync(0xffffffffu, s, off);
    if (lane == 0) sred[warp] = s;
    __syncthreads();
    s = 0.0f;
    #pragma unroll
    for (int w = 0; w < 8; w++) s += sred[w];

    const float inv = 1.0f / s;
    #pragma unroll
    for (int i = 0; i < 16; i++)
        p[tid + i * 256] = v[i] * inv;
}

// ---------------------------------------------------------------------------
extern "C" void kernel_launch(void* const* d_in, const int* in_sizes, int n_in,
                              void* d_out, int out_size)
{
    const float* x    = (const float*)d_in[0];
    const int*   mask = (const int*)  d_in[1];
    const float* Wk   = (const float*)d_in[2];
    const float* Wq   = (const float*)d_in[3];
    const float* Wv   = (const float*)d_in[4];
    float*       out  = (float*)d_out;

    float *pK, *pQ, *pV, *pVt, *pP;
    cudaGetSymbolAddress((void**)&pK,  g_K);
    cudaGetSymbolAddress((void**)&pQ,  g_Q);
    cudaGetSymbolAddress((void**)&pV,  g_V);
    cudaGetSymbolAddress((void**)&pVt, g_Vt);
    cudaGetSymbolAddress((void**)&pP,  g_P);

    const float scale = 0.044194173824159216f;   // 1/sqrt(512)

    // 1) QKV projections: [16384,512] = x @ W^T
    {
        dim3 grid(DIM / 128, (BATCH * SEQ) / 128);
        gemm_abt_kernel<false><<<grid, 256>>>(x, Wk, pK, BATCH * SEQ, DIM, DIM, 1.0f, nullptr);
        gemm_abt_kernel<false><<<grid, 256>>>(x, Wq, pQ, BATCH * SEQ, DIM, DIM, 1.0f, nullptr);
        gemm_abt_kernel<false><<<grid, 256>>>(x, Wv, pV, BATCH * SEQ, DIM, DIM, 1.0f, nullptr);
    }

    // 2) V -> V^T (per batch)
    {
        dim3 grid(DIM / 32, SEQ / 32, BATCH);
        transpose_v_kernel<<<grid, dim3(32, 8)>>>(pV, pVt);
    }

    // 3) scores[b,s,t] = scale * <K[b,s], Q[b,t]>, masked on t
    for (int b = 0; b < BATCH; b++) {
        dim3 grid(SEQ / 128, SEQ / 128);
        gemm_abt_kernel<true><<<grid, 256>>>(
            pK + (size_t)b * SEQ * DIM,
            pQ + (size_t)b * SEQ * DIM,
            pP + (size_t)b * SEQ * SEQ,
            SEQ, SEQ, DIM, scale, mask + (size_t)b * SEQ);
    }

    // 4) softmax over t (rows of length SEQ), in place
    softmax_rows_kernel<<<BATCH * SEQ, 256>>>(pP);

    // 5) out[b,s,d] = sum_t P[b,s,t] * V[b,t,d]  (B operand = V^T, K-major)
    for (int b = 0; b < BATCH; b++) {
        dim3 grid(DIM / 128, SEQ / 128);
        gemm_abt_kernel<false><<<grid, 256>>>(
            pP  + (size_t)b * SEQ * SEQ,
            pVt + (size_t)b * DIM * SEQ,
            out + (size_t)b * SEQ * DIM,
            SEQ, DIM, SEQ, 1.0f, nullptr);
    }
}

// round 3
// speedup vs baseline: 1.8287x; 1.8287x over previous
#include <cuda_runtime.h>
#include <cuda_bf16.h>
#include <cstdint>
#include <cstddef>

#define BATCH 4
#define SEQ   4096
#define DIM   512
#define K3Q   (3 * DIM)   // 1536: split-triple K for projections & scores
#define K3P   (3 * SEQ)   // 12288: split-triple K for P @ V

// ------------------------- scratch (device globals) -------------------------
__device__ __align__(128) __nv_bfloat16 g_x3 [BATCH * SEQ * K3Q];          // [16384,1536] HHL
__device__ __align__(128) __nv_bfloat16 g_Wk3[DIM * K3Q];                  // [512,1536]  HLH
__device__ __align__(128) __nv_bfloat16 g_Wq3[DIM * K3Q];
__device__ __align__(128) __nv_bfloat16 g_Wv3[DIM * K3Q];
__device__ __align__(128) __nv_bfloat16 g_K3 [BATCH * SEQ * K3Q];          // HHL (A of scores)
__device__ __align__(128) __nv_bfloat16 g_Q3 [BATCH * SEQ * K3Q];          // HLH (B of scores)
__device__ __align__(128) float         g_V  [BATCH * SEQ * DIM];
__device__ __align__(128) __nv_bfloat16 g_Vt3[(size_t)BATCH * DIM * K3P];  // [512,12288] HLH
__device__ __align__(128) float         g_P  [(size_t)BATCH * SEQ * SEQ];
__device__ __align__(128) __nv_bfloat16 g_P3 [(size_t)BATCH * SEQ * K3P];  // [16384,12288] HHL

// ------------------------------ PTX helpers --------------------------------
__device__ __forceinline__ uint32_t smem_u32(const void* p) {
    uint32_t a;
    asm("{ .reg .u64 t; cvta.to.shared.u64 t, %1; cvt.u32.u64 %0, t; }" : "=r"(a) : "l"(p));
    return a;
}
__device__ __forceinline__ void cp16(uint32_t s, const void* g) {
    asm volatile("cp.async.cg.shared.global [%0], [%1], 16;" :: "r"(s), "l"(g));
}
__device__ __forceinline__ void cp_commit() {
    asm volatile("cp.async.commit_group;" ::: "memory");
}
template <int N>
__device__ __forceinline__ void cp_wait() {
    asm volatile("cp.async.wait_group %0;" :: "n"(N) : "memory");
}
__device__ __forceinline__ void mma16816(float* d, const uint32_t* a, const uint32_t* b) {
    asm volatile(
        "mma.sync.aligned.m16n8k16.row.col.f32.bf16.bf16.f32 "
        "{%0,%1,%2,%3}, {%4,%5,%6,%7}, {%8,%9}, {%0,%1,%2,%3};"
        : "+f"(d[0]), "+f"(d[1]), "+f"(d[2]), "+f"(d[3])
        : "r"(a[0]), "r"(a[1]), "r"(a[2]), "r"(a[3]), "r"(b[0]), "r"(b[1]));
}

// ---------------------------------------------------------------------------
// bf16 warp-MMA GEMM: C[m,n] = alpha * sum_k A[m,k] * B[n,k]
// A: M x K row-major, B: N x K row-major (both bf16, K multiple of 64).
// CTA tile 128x128, BK=64, 4-stage cp.async pipeline, 8 warps (2m x 4n),
// warp tile 64x32 via mma.sync m16n8k16.
// MODE 0: fp32 C.
// MODE 1: split-bf16 triple out: hi at col, hi at col+offH, lo at col+offL
//         (row stride Nout).
// MODE 2: fp32 C with alpha scale then scatter mask (mask[col]==0 -> -1e12).
// ---------------------------------------------------------------------------
#define BM 128
#define BN 128
#define BK 64
#define STAGES 4
#define ASTR 144                       // smem row bytes: 64*2 + 16 pad (bank-clean)
#define HALF_STAGE (128 * ASTR)        // 18432
#define STAGE_BYTES (2 * HALF_STAGE)   // 36864 (A then B)
#define GSMEM (STAGES * STAGE_BYTES)   // 147456

template <int MODE>
__global__ void __launch_bounds__(256, 1)
gemm_mma(const __nv_bfloat16* __restrict__ A, const __nv_bfloat16* __restrict__ B,
         float* __restrict__ Cf, __nv_bfloat16* __restrict__ Cb,
         int N, int K, size_t Az, size_t Bz, size_t Cz,
         int offH, int offL, int Nout,
         float alpha, const int* __restrict__ mask)
{
    extern __shared__ __align__(128) char smem[];

    const int tid  = threadIdx.x;
    const int z    = blockIdx.z;
    const int bm   = blockIdx.y * BM;
    const int bn   = blockIdx.x * BN;
    const int wid  = tid >> 5;
    const int lane = tid & 31;
    const int wm   = wid >> 2;          // 0..1
    const int wn   = wid & 3;           // 0..3
    const int lr   = lane >> 2;         // 0..7
    const int lc   = lane & 3;          // 0..3

    const __nv_bfloat16* Ag = A + (size_t)z * Az + (size_t)bm * K;
    const __nv_bfloat16* Bg = B + (size_t)z * Bz + (size_t)bn * K;

    // cp.async mapping: 128 rows x 8 x16B chunks per matrix; 4 chunks/thread each
    const int ldrow = tid >> 1;
    const int ldc0  = (tid & 1) * 4;

    float acc[4][4][4];
    #pragma unroll
    for (int mt = 0; mt < 4; mt++)
        #pragma unroll
        for (int nt = 0; nt < 4; nt++)
            #pragma unroll
            for (int j = 0; j < 4; j++) acc[mt][nt][j] = 0.0f;

    const int NC = K / BK;

    auto load_stage = [&](int s, int kblk) {
        char* sa = smem + s * STAGE_BYTES;
        char* sb = sa + HALF_STAGE;
        const __nv_bfloat16* ga = Ag + (size_t)kblk * BK + (size_t)ldrow * K;
        const __nv_bfloat16* gb = Bg + (size_t)kblk * BK + (size_t)ldrow * K;
        const uint32_t soa = smem_u32(sa + ldrow * ASTR);
        const uint32_t sob = smem_u32(sb + ldrow * ASTR);
        #pragma unroll
        for (int j = 0; j < 4; j++) {
            const int c = ldc0 + j;
            cp16(soa + c * 16, ga + c * 8);
            cp16(sob + c * 16, gb + c * 8);
        }
    };

    // prologue: stages 0..STAGES-2
    #pragma unroll
    for (int s = 0; s < STAGES - 1; s++) {
        load_stage(s, s);
        cp_commit();
    }

    for (int i = 0; i < NC; i++) {
        const int pf = i + STAGES - 1;
        if (pf < NC) load_stage(pf % STAGES, pf);
        cp_commit();
        cp_wait<STAGES - 1>();
        __syncthreads();

        const char* sa = smem + (i % STAGES) * STAGE_BYTES;
        const char* sb = sa + HALF_STAGE;

        #pragma unroll
        for (int k16 = 0; k16 < BK / 16; k16++) {
            uint32_t af[4][4], bf[4][2];
            #pragma unroll
            for (int mt = 0; mt < 4; mt++) {
                const char* p = sa + (wm * 64 + mt * 16 + lr) * ASTR
                                   + (k16 * 16 + lc * 2) * 2;
                af[mt][0] = *(const uint32_t*)(p);
                af[mt][1] = *(const uint32_t*)(p + 8 * ASTR);
                af[mt][2] = *(const uint32_t*)(p + 16);
                af[mt][3] = *(const uint32_t*)(p + 8 * ASTR + 16);
            }
            #pragma unroll
            for (int nt = 0; nt < 4; nt++) {
                const char* p = sb + (wn * 32 + nt * 8 + lr) * ASTR
                                   + (k16 * 16 + lc * 2) * 2;
                bf[nt][0] = *(const uint32_t*)(p);
                bf[nt][1] = *(const uint32_t*)(p + 16);
            }
            #pragma unroll
            for (int mt = 0; mt < 4; mt++)
                #pragma unroll
                for (int nt = 0; nt < 4; nt++)
                    mma16816(acc[mt][nt], af[mt], bf[nt]);
        }
        __syncthreads();
    }

    // ------------------------------ epilogue -------------------------------
    #pragma unroll
    for (int mt = 0; mt < 4; mt++) {
        const int r0 = bm + wm * 64 + mt * 16 + lr;
        #pragma unroll
        for (int half = 0; half < 2; half++) {
            const int row = r0 + half * 8;
            #pragma unroll
            for (int nt = 0; nt < 4; nt++) {
                const int col = bn + wn * 32 + nt * 8 + lc * 2;
                float v0 = acc[mt][nt][half * 2 + 0];
                float v1 = acc[mt][nt][half * 2 + 1];
                if (MODE == 1) {
                    __nv_bfloat16 h0 = __float2bfloat16(v0);
                    __nv_bfloat16 h1 = __float2bfloat16(v1);
                    __nv_bfloat16 l0 = __float2bfloat16(v0 - __bfloat162float(h0));
                    __nv_bfloat16 l1 = __float2bfloat16(v1 - __bfloat162float(h1));
                    __nv_bfloat162 hp; hp.x = h0; hp.y = h1;
                    __nv_bfloat162 lp; lp.x = l0; lp.y = l1;
                    __nv_bfloat16* base = Cb + (size_t)z * Cz + (size_t)row * Nout + col;
                    *reinterpret_cast<__nv_bfloat162*>(base)        = hp;
                    *reinterpret_cast<__nv_bfloat162*>(base + offH) = hp;
                    *reinterpret_cast<__nv_bfloat162*>(base + offL) = lp;
                } else {
                    if (MODE == 2) {
                        const int* mz = mask + z * SEQ;
                        v0 *= alpha;
                        v1 *= alpha;
                        if (mz[col] == 0)     v0 = -1e12f;
                        if (mz[col + 1] == 0) v1 = -1e12f;
                    }
                    float2 v = make_float2(v0, v1);
                    *reinterpret_cast<float2*>(Cf + (size_t)z * Cz + (size_t)row * N + col) = v;
                }
            }
        }
    }
}

// ----------------- fp32 -> split-bf16 triple (row-expanded 3x) -------------
// out row r (stride 3*nc): hi at c, hi at c+offH, lo at c+offL
__global__ void split3_kernel(const float* __restrict__ in,
                              __nv_bfloat16* __restrict__ out,
                              int nc, int offH, int offL, int n)
{
    int i = blockIdx.x * blockDim.x + threadIdx.x;
    if (i < n) {
        const int row = i / nc;
        const int c   = i - row * nc;
        const float v = in[i];
        const __nv_bfloat16 h = __float2bfloat16(v);
        const __nv_bfloat16 l = __float2bfloat16(v - __bfloat162float(h));
        __nv_bfloat16* o = out + (size_t)row * (3 * nc);
        o[c]        = h;
        o[c + offH] = h;
        o[c + offL] = l;
    }
}

// V fp32 [b][t][d] -> Vt3 [b][d][12288] HLH: hi at t and 8192+t, lo at 4096+t
__global__ void transpose_split3_kernel(const float* __restrict__ Vin,
                                        __nv_bfloat16* __restrict__ T3)
{
    __shared__ float tile[32][33];
    const int b = blockIdx.z;
    const float* V = Vin + (size_t)b * SEQ * DIM;
    __nv_bfloat16* O = T3 + (size_t)b * DIM * K3P;
    const int d0 = blockIdx.x * 32;
    const int t0 = blockIdx.y * 32;

    #pragma unroll
    for (int r = 0; r < 32; r += 8)
        tile[threadIdx.y + r][threadIdx.x] =
            V[(size_t)(t0 + threadIdx.y + r) * DIM + d0 + threadIdx.x];
    __syncthreads();
    #pragma unroll
    for (int r = 0; r < 32; r += 8) {
        const float v = tile[threadIdx.x][threadIdx.y + r];
        const __nv_bfloat16 h = __float2bfloat16(v);
        const __nv_bfloat16 l = __float2bfloat16(v - __bfloat162float(h));
        __nv_bfloat16* o = O + (size_t)(d0 + threadIdx.y + r) * K3P + t0 + threadIdx.x;
        o[0]            = h;
        o[2 * SEQ]      = h;
        o[SEQ]          = l;
    }
}

// row softmax: fp32 scores -> P3 HHL: hi at t, t+4096; lo at t+8192
__global__ __launch_bounds__(256)
void softmax_kernel(const float* __restrict__ P, __nv_bfloat16* __restrict__ P3)
{
    const size_t rb  = (size_t)blockIdx.x * SEQ;
    const size_t rb3 = (size_t)blockIdx.x * K3P;
    const int tid  = threadIdx.x;
    const int lane = tid & 31;
    const int warp = tid >> 5;
    __shared__ float sred[8];

    float v[16];
    float m = -3.402823466e+38f;
    #pragma unroll
    for (int i = 0; i < 16; i++) {
        v[i] = P[rb + tid + i * 256];
        m = fmaxf(m, v[i]);
    }
    #pragma unroll
    for (int off = 16; off > 0; off >>= 1)
        m = fmaxf(m, __shfl_xor_sync(0xffffffffu, m, off));
    if (lane == 0) sred[warp] = m;
    __syncthreads();
    m = sred[0];
    #pragma unroll
    for (int w = 1; w < 8; w++) m = fmaxf(m, sred[w]);
    __syncthreads();

    float s = 0.0f;
    #pragma unroll
    for (int i = 0; i < 16; i++) {
        v[i] = __expf(v[i] - m);
        s += v[i];
    }
    #pragma unroll
    for (int off = 16; off > 0; off >>= 1)
        s += __shfl_xor_sync(0xffffffffu, s, off);
    if (lane == 0) sred[warp] = s;
    __syncthreads();
    s = 0.0f;
    #pragma unroll
    for (int w = 0; w < 8; w++) s += sred[w];

    const float inv = 1.0f / s;
    #pragma unroll
    for (int i = 0; i < 16; i++) {
        const float w = v[i] * inv;
        const __nv_bfloat16 h = __float2bfloat16(w);
        const __nv_bfloat16 l = __float2bfloat16(w - __bfloat162float(h));
        const int t = tid + i * 256;
        P3[rb3 + t]           = h;
        P3[rb3 + SEQ + t]     = h;
        P3[rb3 + 2 * SEQ + t] = l;
    }
}

// ---------------------------------------------------------------------------
extern "C" void kernel_launch(void* const* d_in, const int* in_sizes, int n_in,
                              void* d_out, int out_size)
{
    const float* x    = (const float*)d_in[0];
    const int*   mask = (const int*)  d_in[1];
    const float* Wk   = (const float*)d_in[2];
    const float* Wq   = (const float*)d_in[3];
    const float* Wv   = (const float*)d_in[4];
    float*       out  = (float*)d_out;

    __nv_bfloat16 *x3, *wk3, *wq3, *wv3, *k3, *q3, *vt3, *p3;
    float *vf, *pf;
    cudaGetSymbolAddress((void**)&x3,  g_x3);
    cudaGetSymbolAddress((void**)&wk3, g_Wk3);
    cudaGetSymbolAddress((void**)&wq3, g_Wq3);
    cudaGetSymbolAddress((void**)&wv3, g_Wv3);
    cudaGetSymbolAddress((void**)&k3,  g_K3);
    cudaGetSymbolAddress((void**)&q3,  g_Q3);
    cudaGetSymbolAddress((void**)&vf,  g_V);
    cudaGetSymbolAddress((void**)&vt3, g_Vt3);
    cudaGetSymbolAddress((void**)&pf,  g_P);
    cudaGetSymbolAddress((void**)&p3,  g_P3);

    cudaFuncSetAttribute(gemm_mma<0>, cudaFuncAttributeMaxDynamicSharedMemorySize, GSMEM);
    cudaFuncSetAttribute(gemm_mma<1>, cudaFuncAttributeMaxDynamicSharedMemorySize, GSMEM);
    cudaFuncSetAttribute(gemm_mma<2>, cudaFuncAttributeMaxDynamicSharedMemorySize, GSMEM);

    const float scale = 0.044194173824159216f;  // 1/sqrt(512)
    const int nx = BATCH * SEQ * DIM;
    const int nw = DIM * DIM;

    // 1) split inputs into K-expanded triples
    split3_kernel<<<(nx + 255) / 256, 256>>>(x,  x3,  DIM, DIM,     2 * DIM, nx);  // HHL
    split3_kernel<<<(nw + 255) / 256, 256>>>(Wk, wk3, DIM, 2 * DIM, DIM,     nw);  // HLH
    split3_kernel<<<(nw + 255) / 256, 256>>>(Wq, wq3, DIM, 2 * DIM, DIM,     nw);  // HLH
    split3_kernel<<<(nw + 255) / 256, 256>>>(Wv, wv3, DIM, 2 * DIM, DIM,     nw);  // HLH

    // 2) QKV projections: M=16384, N=512, K'=1536
    {
        dim3 g(DIM / BN, (BATCH * SEQ) / BM, 1);
        // K -> K3 (HHL: hi@c, hi@c+512, lo@c+1024)
        gemm_mma<1><<<g, 256, GSMEM>>>(x3, wk3, nullptr, k3,
                                       DIM, K3Q, 0, 0, 0,
                                       DIM, 2 * DIM, K3Q, 1.0f, nullptr);
        // Q -> Q3 (HLH: hi@c, hi@c+1024, lo@c+512)
        gemm_mma<1><<<g, 256, GSMEM>>>(x3, wq3, nullptr, q3,
                                       DIM, K3Q, 0, 0, 0,
                                       2 * DIM, DIM, K3Q, 1.0f, nullptr);
        // V -> fp32
        gemm_mma<0><<<g, 256, GSMEM>>>(x3, wv3, vf, nullptr,
                                       DIM, K3Q, 0, 0, 0,
                                       0, 0, 0, 1.0f, nullptr);
    }

    // 3) V -> Vt3
    transpose_split3_kernel<<<dim3(DIM / 32, SEQ / 32, BATCH), dim3(32, 8)>>>(vf, vt3);

    // 4) scores[b,s,t] = scale * <K[b,s], Q[b,t]>, mask on t
    {
        dim3 g(SEQ / BN, SEQ / BM, BATCH);
        gemm_mma<2><<<g, 256, GSMEM>>>(k3, q3, pf, nullptr,
                                       SEQ, K3Q,
                                       (size_t)SEQ * K3Q, (size_t)SEQ * K3Q,
                                       (size_t)SEQ * SEQ,
                                       0, 0, 0, scale, mask);
    }

    // 5) softmax rows -> P3
    softmax_kernel<<<BATCH * SEQ, 256>>>(pf, p3);

    // 6) out[b,s,d] = sum_t P[b,s,t] * V[b,t,d]  (M=4096, N=512, K'=12288)
    {
        dim3 g(DIM / BN, SEQ / BM, BATCH);
        gemm_mma<0><<<g, 256, GSMEM>>>(p3, vt3, out, nullptr,
                                       DIM, K3P,
                                       (size_t)SEQ * K3P, (size_t)DIM * K3P,
                                       (size_t)SEQ * DIM,
                                       0, 0, 0, 1.0f, nullptr);
    }
}

// round 4
// speedup vs baseline: 2.1592x; 1.1807x over previous
#include <cuda_runtime.h>
#include <cuda_bf16.h>
#include <cstdint>
#include <cstddef>

#define BATCH 4
#define SEQ   4096
#define DIM   512
#define K3Q   (3 * DIM)   // 1536: split-triple K for projections & scores
#define K3P   (3 * SEQ)   // 12288: split-triple K for P @ V

// ------------------------- scratch (device globals) -------------------------
__device__ __align__(128) __nv_bfloat16 g_x3 [BATCH * SEQ * K3Q];          // [16384,1536] HHL
__device__ __align__(128) __nv_bfloat16 g_Wk3[DIM * K3Q];                  // [512,1536]  HLH
__device__ __align__(128) __nv_bfloat16 g_Wq3[DIM * K3Q];
__device__ __align__(128) __nv_bfloat16 g_Wv3[DIM * K3Q];
__device__ __align__(128) __nv_bfloat16 g_K3 [BATCH * SEQ * K3Q];          // HHL (A of scores)
__device__ __align__(128) __nv_bfloat16 g_Q3 [BATCH * SEQ * K3Q];          // HLH (B of scores)
__device__ __align__(128) float         g_V  [BATCH * SEQ * DIM];
__device__ __align__(128) __nv_bfloat16 g_Vt3[(size_t)BATCH * DIM * K3P];  // [512,12288] HLH
__device__ __align__(128) float         g_P  [(size_t)BATCH * SEQ * SEQ];
__device__ __align__(128) __nv_bfloat16 g_P3 [(size_t)BATCH * SEQ * K3P];  // [16384,12288] HHL

// ------------------------------ PTX helpers --------------------------------
__device__ __forceinline__ uint32_t smem_u32(const void* p) {
    uint32_t a;
    asm("{ .reg .u64 t; cvta.to.shared.u64 t, %1; cvt.u32.u64 %0, t; }" : "=r"(a) : "l"(p));
    return a;
}
__device__ __forceinline__ void cp16(uint32_t s, const void* g) {
    asm volatile("cp.async.cg.shared.global [%0], [%1], 16;" :: "r"(s), "l"(g));
}
__device__ __forceinline__ void cp_commit() {
    asm volatile("cp.async.commit_group;" ::: "memory");
}
template <int N>
__device__ __forceinline__ void cp_wait() {
    asm volatile("cp.async.wait_group %0;" :: "n"(N) : "memory");
}
__device__ __forceinline__ void mma16816(float* d, const uint32_t* a, const uint32_t* b) {
    asm volatile(
        "mma.sync.aligned.m16n8k16.row.col.f32.bf16.bf16.f32 "
        "{%0,%1,%2,%3}, {%4,%5,%6,%7}, {%8,%9}, {%0,%1,%2,%3};"
        : "+f"(d[0]), "+f"(d[1]), "+f"(d[2]), "+f"(d[3])
        : "r"(a[0]), "r"(a[1]), "r"(a[2]), "r"(a[3]), "r"(b[0]), "r"(b[1]));
}
__device__ __forceinline__ void ldsm4(uint32_t* r, uint32_t addr) {
    asm volatile("ldmatrix.sync.aligned.m8n8.x4.shared.b16 {%0,%1,%2,%3}, [%4];"
                 : "=r"(r[0]), "=r"(r[1]), "=r"(r[2]), "=r"(r[3]) : "r"(addr));
}

// ---------------------------------------------------------------------------
// bf16 warp-MMA GEMM: C[m,n] = alpha * sum_k A[m,k] * B[n,k]
// CTA tile 128x128, BK=64, 3-stage cp.async pipeline, 2 CTAs/SM,
// 8 warps (2m x 4n), warp tile 64x32, ldmatrix fragment loads.
// MODE 0: fp32 C.  MODE 1: split-bf16 triple out (hi@col, hi@col+offH,
// lo@col+offL, row stride Nout).  MODE 2: fp32, alpha scale + scatter mask.
// ---------------------------------------------------------------------------
#define BM 128
#define BN 128
#define BK 64
#define STAGES 3
#define ASTR 144                       // smem row bytes: 64*2 + 16 pad (bank-clean)
#define HALF_STAGE (128 * ASTR)        // 18432
#define STAGE_BYTES (2 * HALF_STAGE)   // 36864 (A then B)
#define GSMEM (STAGES * STAGE_BYTES)   // 110592

template <int MODE>
__global__ void __launch_bounds__(256, 2)
gemm_mma(const __nv_bfloat16* __restrict__ A, const __nv_bfloat16* __restrict__ B,
         float* __restrict__ Cf, __nv_bfloat16* __restrict__ Cb,
         int N, int K, size_t Az, size_t Bz, size_t Cz,
         int offH, int offL, int Nout,
         float alpha, const int* __restrict__ mask)
{
    extern __shared__ __align__(128) char smem[];
    const uint32_t sbase = smem_u32(smem);

    const int tid  = threadIdx.x;
    const int z    = blockIdx.z;
    const int bm   = blockIdx.y * BM;
    const int bn   = blockIdx.x * BN;
    const int wid  = tid >> 5;
    const int lane = tid & 31;
    const int wm   = wid >> 2;          // 0..1
    const int wn   = wid & 3;           // 0..3
    const int lr   = lane >> 2;         // 0..7
    const int lc   = lane & 3;          // 0..3

    const __nv_bfloat16* Ag = A + (size_t)z * Az + (size_t)bm * K;
    const __nv_bfloat16* Bg = B + (size_t)z * Bz + (size_t)bn * K;

    // cp.async mapping: 128 rows x 8 x16B chunks per matrix; 4 chunks/thread each
    const int ldrow = tid >> 1;
    const int ldc0  = (tid & 1) * 4;

    // ldmatrix per-lane offsets (within a stage half)
    //   A: matrices [m0-7/k0-7, m8-15/k0-7, m0-7/k8-15, m8-15/k8-15]
    const uint32_t a_off = (uint32_t)((wm * 64 + ((lane >> 3) & 1) * 8 + (lane & 7)) * ASTR
                                      + (lane >> 4) * 16);
    //   B: matrices [n0-7/k0-7, n0-7/k8-15, n8-15/k0-7, n8-15/k8-15]
    const uint32_t b_off = (uint32_t)((wn * 32 + ((lane >> 4) & 1) * 8 + (lane & 7)) * ASTR
                                      + ((lane >> 3) & 1) * 16);

    float acc[4][4][4];
    #pragma unroll
    for (int mt = 0; mt < 4; mt++)
        #pragma unroll
        for (int nt = 0; nt < 4; nt++)
            #pragma unroll
            for (int j = 0; j < 4; j++) acc[mt][nt][j] = 0.0f;

    const int NC = K / BK;

    auto load_stage = [&](int s, int kblk) {
        char* sa = smem + s * STAGE_BYTES;
        char* sb = sa + HALF_STAGE;
        const __nv_bfloat16* ga = Ag + (size_t)kblk * BK + (size_t)ldrow * K;
        const __nv_bfloat16* gb = Bg + (size_t)kblk * BK + (size_t)ldrow * K;
        const uint32_t soa = smem_u32(sa + ldrow * ASTR);
        const uint32_t sob = smem_u32(sb + ldrow * ASTR);
        #pragma unroll
        for (int j = 0; j < 4; j++) {
            const int c = ldc0 + j;
            cp16(soa + c * 16, ga + c * 8);
            cp16(sob + c * 16, gb + c * 8);
        }
    };

    #pragma unroll
    for (int s = 0; s < STAGES - 1; s++) {
        load_stage(s, s);
        cp_commit();
    }

    for (int i = 0; i < NC; i++) {
        const int pf = i + STAGES - 1;
        if (pf < NC) load_stage(pf % STAGES, pf);
        cp_commit();
        cp_wait<STAGES - 1>();
        __syncthreads();

        const uint32_t sa = sbase + (i % STAGES) * STAGE_BYTES;
        const uint32_t sb = sa + HALF_STAGE;

        #pragma unroll
        for (int k16 = 0; k16 < BK / 16; k16++) {
            uint32_t af[4][4], bf[4][2];
            #pragma unroll
            for (int mt = 0; mt < 4; mt++)
                ldsm4(af[mt], sa + a_off + mt * (16 * ASTR) + k16 * 32);
            #pragma unroll
            for (int ntp = 0; ntp < 2; ntp++) {
                uint32_t br[4];
                ldsm4(br, sb + b_off + ntp * (16 * ASTR) + k16 * 32);
                bf[ntp * 2 + 0][0] = br[0];
                bf[ntp * 2 + 0][1] = br[1];
                bf[ntp * 2 + 1][0] = br[2];
                bf[ntp * 2 + 1][1] = br[3];
            }
            #pragma unroll
            for (int mt = 0; mt < 4; mt++)
                #pragma unroll
                for (int nt = 0; nt < 4; nt++)
                    mma16816(acc[mt][nt], af[mt], bf[nt]);
        }
        __syncthreads();
    }

    // ------------------------------ epilogue -------------------------------
    #pragma unroll
    for (int mt = 0; mt < 4; mt++) {
        const int r0 = bm + wm * 64 + mt * 16 + lr;
        #pragma unroll
        for (int half = 0; half < 2; half++) {
            const int row = r0 + half * 8;
            #pragma unroll
            for (int nt = 0; nt < 4; nt++) {
                const int col = bn + wn * 32 + nt * 8 + lc * 2;
                float v0 = acc[mt][nt][half * 2 + 0];
                float v1 = acc[mt][nt][half * 2 + 1];
                if (MODE == 1) {
                    __nv_bfloat16 h0 = __float2bfloat16(v0);
                    __nv_bfloat16 h1 = __float2bfloat16(v1);
                    __nv_bfloat16 l0 = __float2bfloat16(v0 - __bfloat162float(h0));
                    __nv_bfloat16 l1 = __float2bfloat16(v1 - __bfloat162float(h1));
                    __nv_bfloat162 hp; hp.x = h0; hp.y = h1;
                    __nv_bfloat162 lp; lp.x = l0; lp.y = l1;
                    __nv_bfloat16* base = Cb + (size_t)z * Cz + (size_t)row * Nout + col;
                    *reinterpret_cast<__nv_bfloat162*>(base)        = hp;
                    *reinterpret_cast<__nv_bfloat162*>(base + offH) = hp;
                    *reinterpret_cast<__nv_bfloat162*>(base + offL) = lp;
                } else {
                    if (MODE == 2) {
                        const int* mz = mask + z * SEQ;
                        v0 *= alpha;
                        v1 *= alpha;
                        if (mz[col] == 0)     v0 = -1e12f;
                        if (mz[col + 1] == 0) v1 = -1e12f;
                    }
                    float2 v = make_float2(v0, v1);
                    *reinterpret_cast<float2*>(Cf + (size_t)z * Cz + (size_t)row * N + col) = v;
                }
            }
        }
    }
}

// ----------------- fp32 -> split-bf16 triple (row-expanded 3x) -------------
__global__ void split3_kernel(const float* __restrict__ in,
                              __nv_bfloat16* __restrict__ out,
                              int nc, int offH, int offL, int n)
{
    int i = blockIdx.x * blockDim.x + threadIdx.x;
    if (i < n) {
        const int row = i / nc;
        const int c   = i - row * nc;
        const float v = in[i];
        const __nv_bfloat16 h = __float2bfloat16(v);
        const __nv_bfloat16 l = __float2bfloat16(v - __bfloat162float(h));
        __nv_bfloat16* o = out + (size_t)row * (3 * nc);
        o[c]        = h;
        o[c + offH] = h;
        o[c + offL] = l;
    }
}

// V fp32 [b][t][d] -> Vt3 [b][d][12288] HLH: hi at t and 8192+t, lo at 4096+t
__global__ void transpose_split3_kernel(const float* __restrict__ Vin,
                                        __nv_bfloat16* __restrict__ T3)
{
    __shared__ float tile[32][33];
    const int b = blockIdx.z;
    const float* V = Vin + (size_t)b * SEQ * DIM;
    __nv_bfloat16* O = T3 + (size_t)b * DIM * K3P;
    const int d0 = blockIdx.x * 32;
    const int t0 = blockIdx.y * 32;

    #pragma unroll
    for (int r = 0; r < 32; r += 8)
        tile[threadIdx.y + r][threadIdx.x] =
            V[(size_t)(t0 + threadIdx.y + r) * DIM + d0 + threadIdx.x];
    __syncthreads();
    #pragma unroll
    for (int r = 0; r < 32; r += 8) {
        const float v = tile[threadIdx.x][threadIdx.y + r];
        const __nv_bfloat16 h = __float2bfloat16(v);
        const __nv_bfloat16 l = __float2bfloat16(v - __bfloat162float(h));
        __nv_bfloat16* o = O + (size_t)(d0 + threadIdx.y + r) * K3P + t0 + threadIdx.x;
        o[0]            = h;
        o[2 * SEQ]      = h;
        o[SEQ]          = l;
    }
}

// row softmax: fp32 scores -> P3 HHL: hi at t, t+4096; lo at t+8192
__global__ __launch_bounds__(256)
void softmax_kernel(const float* __restrict__ P, __nv_bfloat16* __restrict__ P3)
{
    const size_t rb  = (size_t)blockIdx.x * SEQ;
    const size_t rb3 = (size_t)blockIdx.x * K3P;
    const int tid  = threadIdx.x;
    const int lane = tid & 31;
    const int warp = tid >> 5;
    __shared__ float sred[8];

    float v[16];
    float m = -3.402823466e+38f;
    #pragma unroll
    for (int i = 0; i < 16; i++) {
        v[i] = P[rb + tid + i * 256];
        m = fmaxf(m, v[i]);
    }
    #pragma unroll
    for (int off = 16; off > 0; off >>= 1)
        m = fmaxf(m, __shfl_xor_sync(0xffffffffu, m, off));
    if (lane == 0) sred[warp] = m;
    __syncthreads();
    m = sred[0];
    #pragma unroll
    for (int w = 1; w < 8; w++) m = fmaxf(m, sred[w]);
    __syncthreads();

    float s = 0.0f;
    #pragma unroll
    for (int i = 0; i < 16; i++) {
        v[i] = __expf(v[i] - m);
        s += v[i];
    }
    #pragma unroll
    for (int off = 16; off > 0; off >>= 1)
        s += __shfl_xor_sync(0xffffffffu, s, off);
    if (lane == 0) sred[warp] = s;
    __syncthreads();
    s = 0.0f;
    #pragma unroll
    for (int w = 0; w < 8; w++) s += sred[w];

    const float inv = 1.0f / s;
    #pragma unroll
    for (int i = 0; i < 16; i++) {
        const float w = v[i] * inv;
        const __nv_bfloat16 h = __float2bfloat16(w);
        const __nv_bfloat16 l = __float2bfloat16(w - __bfloat162float(h));
        const int t = tid + i * 256;
        P3[rb3 + t]           = h;
        P3[rb3 + SEQ + t]     = h;
        P3[rb3 + 2 * SEQ + t] = l;
    }
}

// ---------------------------------------------------------------------------
extern "C" void kernel_launch(void* const* d_in, const int* in_sizes, int n_in,
                              void* d_out, int out_size)
{
    const float* x    = (const float*)d_in[0];
    const int*   mask = (const int*)  d_in[1];
    const float* Wk   = (const float*)d_in[2];
    const float* Wq   = (const float*)d_in[3];
    const float* Wv   = (const float*)d_in[4];
    float*       out  = (float*)d_out;

    __nv_bfloat16 *x3, *wk3, *wq3, *wv3, *k3, *q3, *vt3, *p3;
    float *vf, *pf;
    cudaGetSymbolAddress((void**)&x3,  g_x3);
    cudaGetSymbolAddress((void**)&wk3, g_Wk3);
    cudaGetSymbolAddress((void**)&wq3, g_Wq3);
    cudaGetSymbolAddress((void**)&wv3, g_Wv3);
    cudaGetSymbolAddress((void**)&k3,  g_K3);
    cudaGetSymbolAddress((void**)&q3,  g_Q3);
    cudaGetSymbolAddress((void**)&vf,  g_V);
    cudaGetSymbolAddress((void**)&vt3, g_Vt3);
    cudaGetSymbolAddress((void**)&pf,  g_P);
    cudaGetSymbolAddress((void**)&p3,  g_P3);

    cudaFuncSetAttribute(gemm_mma<0>, cudaFuncAttributeMaxDynamicSharedMemorySize, GSMEM);
    cudaFuncSetAttribute(gemm_mma<1>, cudaFuncAttributeMaxDynamicSharedMemorySize, GSMEM);
    cudaFuncSetAttribute(gemm_mma<2>, cudaFuncAttributeMaxDynamicSharedMemorySize, GSMEM);

    const float scale = 0.044194173824159216f;  // 1/sqrt(512)
    const int nx = BATCH * SEQ * DIM;
    const int nw = DIM * DIM;

    // 1) split inputs into K-expanded triples
    split3_kernel<<<(nx + 255) / 256, 256>>>(x,  x3,  DIM, DIM,     2 * DIM, nx);  // HHL
    split3_kernel<<<(nw + 255) / 256, 256>>>(Wk, wk3, DIM, 2 * DIM, DIM,     nw);  // HLH
    split3_kernel<<<(nw + 255) / 256, 256>>>(Wq, wq3, DIM, 2 * DIM, DIM,     nw);  // HLH
    split3_kernel<<<(nw + 255) / 256, 256>>>(Wv, wv3, DIM, 2 * DIM, DIM,     nw);  // HLH

    // 2) QKV projections: M=16384, N=512, K'=1536
    {
        dim3 g(DIM / BN, (BATCH * SEQ) / BM, 1);
        gemm_mma<1><<<g, 256, GSMEM>>>(x3, wk3, nullptr, k3,
                                       DIM, K3Q, 0, 0, 0,
                                       DIM, 2 * DIM, K3Q, 1.0f, nullptr);   // K -> HHL
        gemm_mma<1><<<g, 256, GSMEM>>>(x3, wq3, nullptr, q3,
                                       DIM, K3Q, 0, 0, 0,
                                       2 * DIM, DIM, K3Q, 1.0f, nullptr);   // Q -> HLH
        gemm_mma<0><<<g, 256, GSMEM>>>(x3, wv3, vf, nullptr,
                                       DIM, K3Q, 0, 0, 0,
                                       0, 0, 0, 1.0f, nullptr);             // V -> fp32
    }

    // 3) V -> Vt3
    transpose_split3_kernel<<<dim3(DIM / 32, SEQ / 32, BATCH), dim3(32, 8)>>>(vf, vt3);

    // 4) scores[b,s,t] = scale * <K[b,s], Q[b,t]>, mask on t
    {
        dim3 g(SEQ / BN, SEQ / BM, BATCH);
        gemm_mma<2><<<g, 256, GSMEM>>>(k3, q3, pf, nullptr,
                                       SEQ, K3Q,
                                       (size_t)SEQ * K3Q, (size_t)SEQ * K3Q,
                                       (size_t)SEQ * SEQ,
                                       0, 0, 0, scale, mask);
    }

    // 5) softmax rows -> P3
    softmax_kernel<<<BATCH * SEQ, 256>>>(pf, p3);

    // 6) out[b,s,d] = sum_t P[b,s,t] * V[b,t,d]  (M=4096, N=512, K'=12288)
    {
        dim3 g(DIM / BN, SEQ / BM, BATCH);
        gemm_mma<0><<<g, 256, GSMEM>>>(p3, vt3, out, nullptr,
                                       DIM, K3P,
                                       (size_t)SEQ * K3P, (size_t)DIM * K3P,
                                       (size_t)SEQ * DIM,
                                       0, 0, 0, 1.0f, nullptr);
    }
}